// round 2
// baseline (speedup 1.0000x reference)
#include <cuda_runtime.h>
#include <cuda_bf16.h>
#include <math.h>

#define BB 4
#define LL 2048
#define KK 30
#define NROW (BB*LL)        // 8192
#define NEDGE (NROW*KK)     // 245760
#define NF 128
#define NC 256              // RBF feature count (K of the GEMM)

// ---------------- device scratch (static globals; no allocations) ------------
__device__ float4 g_atoms[4*NROW];          // atom-major: [atom][row]  N,C,Ca,Cb
__device__ int    g_Eidx[NEDGE];
__device__ float  g_Dnb[NEDGE];
__device__ int    g_dcode[NEDGE];
__device__ float  g_feat[(size_t)NEDGE*NC]; // 251.6 MB fp32 RBF features
__device__ float  g_WRT[NC*NF];             // transposed rbf weights [c][f]
__device__ float  g_PW[66*NF];              // positional lookup [d][f]
__device__ int    g_idx32;

// pair table: block p uses dist(atom pa[p] of i, atom pb[p] of j); atoms N=0,C=1,Ca=2,Cb=3
__constant__ int c_pa[16] = {1,0,2,3,1,1,1,0,0,3,0,2,3,2,3,2};
__constant__ int c_pb[16] = {1,0,2,3,0,2,3,2,3,2,1,1,1,0,0,3};

__device__ __forceinline__ int read_idx(const void* p, int i, int is32) {
    if (is32) return ((const int*)p)[i];
    return (int)((const long long*)p)[i];
}

// ---------------- kernel 0: detect int32 vs int64 residue_idx ----------------
__global__ void k_detect(const void* residx) {
    const int* p = (const int*)residx;
    g_idx32 = (p[1] == 1 && p[2] == 2) ? 1 : 0;
}

// ---------------- kernel 1: per-residue atoms + virtual Cb -------------------
__global__ void k_coords(const float* __restrict__ X) {
    int t = blockIdx.x * blockDim.x + threadIdx.x;
    if (t >= NROW) return;
    const float* x = X + (size_t)t * 12;
    float Nx=x[0],Ny=x[1],Nz=x[2];
    float Cx=x[3],Cy=x[4],Cz=x[5];
    float Ax=x[6],Ay=x[7],Az=x[8];
    float bx=Ax-Nx, by=Ay-Ny, bz=Az-Nz;       // Ca - N
    float cx=Cx-Ax, cy=Cy-Ay, cz=Cz-Az;       // C - Ca
    float ax=by*cz-bz*cy, ay=bz*cx-bx*cz, az=bx*cy-by*cx;
    float Bx = -0.58273431f*ax + 0.56802827f*bx - 0.54067466f*cx + Ax;
    float By = -0.58273431f*ay + 0.56802827f*by - 0.54067466f*cy + Ay;
    float Bz = -0.58273431f*az + 0.56802827f*bz - 0.54067466f*cz + Az;
    g_atoms[0*NROW + t] = make_float4(Nx,Ny,Nz,0.f);
    g_atoms[1*NROW + t] = make_float4(Cx,Cy,Cz,0.f);
    g_atoms[2*NROW + t] = make_float4(Ax,Ay,Az,0.f);
    g_atoms[3*NROW + t] = make_float4(Bx,By,Bz,0.f);
}

// ---------------- kernel 2a: transpose rbf part of edge_w --------------------
__global__ void k_wrt(const float* __restrict__ edge_w) {
    int idx = blockIdx.x * blockDim.x + threadIdx.x;
    if (idx >= NC*NF) return;
    int c = idx / NF, f = idx % NF;
    g_WRT[idx] = edge_w[f*272 + 16 + c];
}

// ---------------- kernel 2b: positional lookup table -------------------------
__global__ void k_pw(const float* __restrict__ edge_w, const float* __restrict__ pe_w,
                     const float* __restrict__ pe_b) {
    int d = blockIdx.x;     // 0..65
    int f = threadIdx.x;    // 0..127
    float s = 0.f;
    #pragma unroll
    for (int n = 0; n < 16; n++)
        s += edge_w[f*272 + n] * (pe_w[n*66 + d] + pe_b[n]);
    g_PW[d*NF + f] = s;
}

// ---------------- kernel 3: top-k (k=30) nearest C-C per row -----------------
__global__ void k_topk(const float* __restrict__ mask, float* __restrict__ out_idx) {
    __shared__ float s_d[LL];
    __shared__ float s_fred[8];
    __shared__ unsigned long long s_red[8];
    __shared__ float s_dmax;

    int row = blockIdx.x;
    int b = row / LL;
    int tid = threadIdx.x;
    int lane = tid & 31, wid = tid >> 5;

    float4 ci = g_atoms[1*NROW + row];
    float mi = mask[row];
    float lmax = 0.f;
    #pragma unroll
    for (int u = 0; u < LL/256; u++) {
        int j = tid + u*256;
        float4 cj = g_atoms[1*NROW + b*LL + j];
        float dx = ci.x-cj.x, dy = ci.y-cj.y, dz = ci.z-cj.z;
        float d = sqrtf(dx*dx + dy*dy + dz*dz + 1e-6f);
        float v = mi * mask[b*LL + j] * d;
        s_d[j] = v;
        lmax = fmaxf(lmax, v);
    }
    // reduce max -> Dmax
    #pragma unroll
    for (int o = 16; o > 0; o >>= 1) lmax = fmaxf(lmax, __shfl_xor_sync(0xffffffffu, lmax, o));
    if (lane == 0) s_fred[wid] = lmax;
    __syncthreads();
    if (wid == 0) {
        float v = (lane < 8) ? s_fred[lane] : 0.f;
        #pragma unroll
        for (int o = 4; o > 0; o >>= 1) v = fmaxf(v, __shfl_xor_sync(0xffffffffu, v, o));
        if (lane == 0) s_dmax = v;
    }
    __syncthreads();
    float Dmax = s_dmax;
    // adjust: D + (1 - m2) * Dmax
    #pragma unroll
    for (int u = 0; u < LL/256; u++) {
        int j = tid + u*256;
        float m2 = mi * mask[b*LL + j];
        s_d[j] += (1.f - m2) * Dmax;
    }
    __syncthreads();

    const unsigned long long UMAX = 0xffffffffffffffffULL;
    for (int sel = 0; sel < KK; sel++) {
        unsigned long long best = UMAX;
        #pragma unroll
        for (int u = 0; u < LL/256; u++) {
            int j = tid + u*256;
            unsigned long long key = ((unsigned long long)__float_as_uint(s_d[j]) << 32) | (unsigned)j;
            best = min(best, key);
        }
        #pragma unroll
        for (int o = 16; o > 0; o >>= 1)
            best = min(best, __shfl_xor_sync(0xffffffffu, best, o));
        if (lane == 0) s_red[wid] = best;
        __syncthreads();
        if (tid == 0) {
            unsigned long long w = s_red[0];
            #pragma unroll
            for (int q = 1; q < 8; q++) w = min(w, s_red[q]);
            int jwin = (int)(w & 0xffffffffu);
            float val = __uint_as_float((unsigned)(w >> 32));
            g_Eidx[row*KK + sel] = jwin;
            g_Dnb[row*KK + sel] = val;
            if (out_idx) out_idx[row*KK + sel] = (float)jwin;
            s_d[jwin] = __int_as_float(0x7f800000); // +inf
        }
        __syncthreads();
    }
}

// ---------------- kernel 4: per-edge RBF features + positional code ----------
__global__ void k_feat(const void* __restrict__ residx, const void* __restrict__ chains) {
    int wid = threadIdx.x >> 5, lane = threadIdx.x & 31;
    int e = blockIdx.x * 8 + wid;
    int row = e / KK;
    int b = row / LL;
    int j = g_Eidx[e];
    int rowj = b*LL + j;
    int is32 = g_idx32;

    float d = 0.f;
    if (lane < 16) {
        if (lane == 0) {
            d = g_Dnb[e];
        } else {
            float4 A = g_atoms[c_pa[lane]*NROW + row];
            float4 Bv = g_atoms[c_pb[lane]*NROW + rowj];
            float dx = A.x-Bv.x, dy = A.y-Bv.y, dz = A.z-Bv.z;
            d = sqrtf(dx*dx + dy*dy + dz*dz + 1e-6f);
        }
    }
    if (lane == 16) {
        int ri = read_idx(residx, row, is32);
        int rj = read_idx(residx, rowj, is32);
        int ci = read_idx(chains, row, is32);
        int cj = read_idx(chains, rowj, is32);
        int off = ri - rj + 32;
        off = max(0, min(64, off));
        int dcode = (ci == cj) ? off : 65;
        g_dcode[e] = dcode;
    }

    float vals[8];
    #pragma unroll
    for (int u = 0; u < 8; u++) {
        int c = lane*8 + u;
        int p = c >> 4, m = c & 15;
        float dp = __shfl_sync(0xffffffffu, d, p);
        float mu = 2.0f + (float)m * (20.0f/15.0f);
        float z = (dp - mu) * 0.8f;        // / 1.25
        vals[u] = expf(-z*z);
    }
    float* dst = g_feat + (size_t)e*NC + lane*8;
    *(float4*)(dst)     = make_float4(vals[0],vals[1],vals[2],vals[3]);
    *(float4*)(dst + 4) = make_float4(vals[4],vals[5],vals[6],vals[7]);
}

// ---------------- kernel 5: GEMM (64 edges x 128 f, K=256) + pos + LayerNorm -
__global__ __launch_bounds__(256) void k_gemm(const float* __restrict__ ln_g,
                                              const float* __restrict__ ln_b,
                                              float* __restrict__ out) {
    __shared__ float A_s[16][68];
    __shared__ float B_s[16][128];

    int tid = threadIdx.x;
    int tx = tid & 31;       // f group: f = tx*4 .. tx*4+3
    int ty = tid >> 5;       // m group: m = ty*4+mm and 32+ty*4+mm
    int e0 = blockIdx.x * 64;

    float4 acc[8];
    #pragma unroll
    for (int i = 0; i < 8; i++) acc[i] = make_float4(0.f,0.f,0.f,0.f);

    int mloc = tid >> 2, q = tid & 3;

    for (int kc = 0; kc < NC; kc += 16) {
        __syncthreads();
        // A tile: 64 edges x 16 c, transposed into A_s[c][m]
        float4 va = *(const float4*)(g_feat + (size_t)(e0 + mloc)*NC + kc + q*4);
        A_s[q*4+0][mloc] = va.x;
        A_s[q*4+1][mloc] = va.y;
        A_s[q*4+2][mloc] = va.z;
        A_s[q*4+3][mloc] = va.w;
        // B tile: 16 c x 128 f
        #pragma unroll
        for (int r = 0; r < 2; r++) {
            int lin = r*256 + tid;          // float4 units
            int c = lin >> 5, fq = lin & 31;
            *(float4*)&B_s[c][fq*4] = *(const float4*)(g_WRT + (kc + c)*NF + fq*4);
        }
        __syncthreads();
        #pragma unroll
        for (int cc = 0; cc < 16; cc++) {
            float4 a0 = *(const float4*)&A_s[cc][ty*4];
            float4 a1 = *(const float4*)&A_s[cc][32 + ty*4];
            float4 bb = *(const float4*)&B_s[cc][tx*4];
            acc[0].x += a0.x*bb.x; acc[0].y += a0.x*bb.y; acc[0].z += a0.x*bb.z; acc[0].w += a0.x*bb.w;
            acc[1].x += a0.y*bb.x; acc[1].y += a0.y*bb.y; acc[1].z += a0.y*bb.z; acc[1].w += a0.y*bb.w;
            acc[2].x += a0.z*bb.x; acc[2].y += a0.z*bb.y; acc[2].z += a0.z*bb.z; acc[2].w += a0.z*bb.w;
            acc[3].x += a0.w*bb.x; acc[3].y += a0.w*bb.y; acc[3].z += a0.w*bb.z; acc[3].w += a0.w*bb.w;
            acc[4].x += a1.x*bb.x; acc[4].y += a1.x*bb.y; acc[4].z += a1.x*bb.z; acc[4].w += a1.x*bb.w;
            acc[5].x += a1.y*bb.x; acc[5].y += a1.y*bb.y; acc[5].z += a1.y*bb.z; acc[5].w += a1.y*bb.w;
            acc[6].x += a1.z*bb.x; acc[6].y += a1.z*bb.y; acc[6].z += a1.z*bb.z; acc[6].w += a1.z*bb.w;
            acc[7].x += a1.w*bb.x; acc[7].y += a1.w*bb.y; acc[7].z += a1.w*bb.z; acc[7].w += a1.w*bb.w;
        }
    }

    // epilogue: add positional, LayerNorm across 128 f (warp = full f for each m)
    float4 gg = *(const float4*)(ln_g + tx*4);
    float4 bbv = *(const float4*)(ln_b + tx*4);
    #pragma unroll
    for (int mm = 0; mm < 8; mm++) {
        int m = (mm < 4) ? (ty*4 + mm) : (32 + ty*4 + (mm - 4));
        int e = e0 + m;
        float4 pw = *(const float4*)(g_PW + g_dcode[e]*NF + tx*4);
        float4 v = acc[mm];
        v.x += pw.x; v.y += pw.y; v.z += pw.z; v.w += pw.w;
        float s  = v.x + v.y + v.z + v.w;
        float s2 = v.x*v.x + v.y*v.y + v.z*v.z + v.w*v.w;
        #pragma unroll
        for (int o = 16; o > 0; o >>= 1) {
            s  += __shfl_xor_sync(0xffffffffu, s,  o);
            s2 += __shfl_xor_sync(0xffffffffu, s2, o);
        }
        float muv = s * (1.f/128.f);
        float var = s2 * (1.f/128.f) - muv*muv;
        float rstd = rsqrtf(var + 1e-5f);
        float4 o4;
        o4.x = (v.x - muv)*rstd*gg.x + bbv.x;
        o4.y = (v.y - muv)*rstd*gg.y + bbv.y;
        o4.z = (v.z - muv)*rstd*gg.z + bbv.z;
        o4.w = (v.w - muv)*rstd*gg.w + bbv.w;
        *(float4*)(out + (size_t)e*NF + tx*4) = o4;
    }
}

// ---------------- launch ------------------------------------------------------
extern "C" void kernel_launch(void* const* d_in, const int* in_sizes, int n_in,
                              void* d_out, int out_size) {
    const float* X      = (const float*)d_in[0];
    const float* mask   = (const float*)d_in[1];
    const void*  residx = d_in[2];
    const void*  chains = d_in[3];
    const float* pe_w   = (const float*)d_in[4];
    const float* pe_b   = (const float*)d_in[5];
    const float* edge_w = (const float*)d_in[6];
    const float* ln_g   = (const float*)d_in[7];
    const float* ln_b   = (const float*)d_in[8];
    float* out = (float*)d_out;
    float* out_idx = ((size_t)out_size >= (size_t)NEDGE*NF + NEDGE)
                     ? out + (size_t)NEDGE*NF : nullptr;

    k_detect<<<1, 1>>>(residx);
    k_coords<<<(NROW + 255)/256, 256>>>(X);
    k_wrt<<<(NC*NF + 255)/256, 256>>>(edge_w);
    k_pw<<<66, 128>>>(edge_w, pe_w, pe_b);
    k_topk<<<NROW, 256>>>(mask, out_idx);
    k_feat<<<NEDGE/8, 256>>>(residx, chains);
    k_gemm<<<NEDGE/64, 256>>>(ln_g, ln_b, out);
}

// round 5
// speedup vs baseline: 1.3803x; 1.3803x over previous
#include <cuda_runtime.h>
#include <cuda_bf16.h>
#include <math.h>
#include <stdint.h>

#define BB 4
#define LL 2048
#define KK 30
#define NROW (BB*LL)        // 8192
#define NEDGE (NROW*KK)     // 245760
#define NTILE (NEDGE/128)   // 1920
#define NF 128
#define NC 256              // RBF feature count (K of the GEMM)

// ---------------- device scratch ---------------------------------------------
__device__ float4   g_atoms[4*NROW];
__device__ int      g_Eidx[NEDGE];
__device__ float    g_Dnb[NEDGE];
__device__ uint32_t g_Bh[16*16*32*2];   // B fragments (bf16 hi), [sg][t][lane][w]
__device__ uint32_t g_Bl[16*16*32*2];   // B fragments (bf16 lo)
__device__ float    g_PW[66*NF];        // positional lookup [dcode][f]
__device__ int      g_idx32;

__constant__ int c_pa[16] = {1,0,2,3,1,1,1,0,0,3,0,2,3,2,3,2};
__constant__ int c_pb[16] = {1,0,2,3,0,2,3,2,3,2,1,1,1,0,0,3};

__device__ __forceinline__ int read_idx(const void* p, int i, int is32) {
    if (is32) return ((const int*)p)[i];
    return (int)((const long long*)p)[i];
}

__device__ __forceinline__ uint32_t pack_bf16x2(float lo_v, float hi_v) {
    __nv_bfloat16 a = __float2bfloat16(lo_v);
    __nv_bfloat16 b = __float2bfloat16(hi_v);
    return (uint32_t)__bfloat16_as_ushort(a) | ((uint32_t)__bfloat16_as_ushort(b) << 16);
}

#define MMA_BF16(d, a0, a1, a2, a3, b0, b1) \
    asm volatile("mma.sync.aligned.m16n8k16.row.col.f32.bf16.bf16.f32 " \
        "{%0,%1,%2,%3}, {%4,%5,%6,%7}, {%8,%9}, {%0,%1,%2,%3};" \
        : "+f"((d)[0]), "+f"((d)[1]), "+f"((d)[2]), "+f"((d)[3]) \
        : "r"(a0), "r"(a1), "r"(a2), "r"(a3), "r"(b0), "r"(b1))

// ---------------- kernel 0: detect int32 vs int64 ----------------------------
__global__ void k_detect(const void* residx) {
    const int* p = (const int*)residx;
    g_idx32 = (p[1] == 1 && p[2] == 2) ? 1 : 0;
}

// ---------------- kernel 1: atoms + virtual Cb -------------------------------
__global__ void k_coords(const float* __restrict__ X) {
    int t = blockIdx.x * blockDim.x + threadIdx.x;
    if (t >= NROW) return;
    const float* x = X + (size_t)t * 12;
    float Nx=x[0],Ny=x[1],Nz=x[2];
    float Cx=x[3],Cy=x[4],Cz=x[5];
    float Ax=x[6],Ay=x[7],Az=x[8];
    float bx=Ax-Nx, by=Ay-Ny, bz=Az-Nz;
    float cx=Cx-Ax, cy=Cy-Ay, cz=Cz-Az;
    float ax=by*cz-bz*cy, ay=bz*cx-bx*cz, az=bx*cy-by*cx;
    float Bx = -0.58273431f*ax + 0.56802827f*bx - 0.54067466f*cx + Ax;
    float By = -0.58273431f*ay + 0.56802827f*by - 0.54067466f*cy + Ay;
    float Bz = -0.58273431f*az + 0.56802827f*bz - 0.54067466f*cz + Az;
    g_atoms[0*NROW + t] = make_float4(Nx,Ny,Nz,0.f);
    g_atoms[1*NROW + t] = make_float4(Cx,Cy,Cz,0.f);
    g_atoms[2*NROW + t] = make_float4(Ax,Ay,Az,0.f);
    g_atoms[3*NROW + t] = make_float4(Bx,By,Bz,0.f);
}

// ---------------- kernel 2a: weights -> mma B-fragment layout (hi/lo) --------
// widx = sg*1024 + t*64 + lane*2 + wsel ; element (n, k):
//   n = t*8 + lane/4 ; k0 = sg*16 + (lane%4)*2 + wsel*8 ; pack (k0, k0+1)
__global__ void k_bfrag(const float* __restrict__ edge_w) {
    int widx = blockIdx.x * blockDim.x + threadIdx.x;
    if (widx >= 16*16*32*2) return;
    int sg   = widx >> 10;
    int t    = (widx >> 6) & 15;
    int lane = (widx >> 1) & 31;
    int wsel = widx & 1;
    int n  = t*8 + (lane >> 2);
    int k0 = sg*16 + (lane & 3)*2 + wsel*8;
    float w0 = edge_w[n*272 + 16 + k0];
    float w1 = edge_w[n*272 + 16 + k0 + 1];
    __nv_bfloat16 h0 = __float2bfloat16(w0);
    __nv_bfloat16 h1 = __float2bfloat16(w1);
    float l0 = w0 - __bfloat162float(h0);
    float l1 = w1 - __bfloat162float(h1);
    g_Bh[widx] = (uint32_t)__bfloat16_as_ushort(h0) | ((uint32_t)__bfloat16_as_ushort(h1) << 16);
    g_Bl[widx] = pack_bf16x2(l0, l1);
}

// ---------------- kernel 2b: positional lookup table -------------------------
__global__ void k_pw(const float* __restrict__ edge_w, const float* __restrict__ pe_w,
                     const float* __restrict__ pe_b) {
    int d = blockIdx.x;
    int f = threadIdx.x;
    float s = 0.f;
    #pragma unroll
    for (int n = 0; n < 16; n++)
        s += edge_w[f*272 + n] * (pe_w[n*66 + d] + pe_b[n]);
    g_PW[d*NF + f] = s;
}

// ---------------- kernel 3: top-k nearest C-C per row ------------------------
__global__ void k_topk(const float* __restrict__ mask, float* __restrict__ out_idx) {
    __shared__ float s_d[LL];
    __shared__ float s_fred[8];
    __shared__ unsigned long long s_red[8];
    __shared__ float s_dmax;

    int row = blockIdx.x;
    int b = row / LL;
    int tid = threadIdx.x;
    int lane = tid & 31, wid = tid >> 5;

    float4 ci = g_atoms[1*NROW + row];
    float mi = mask[row];
    float lmax = 0.f;
    #pragma unroll
    for (int u = 0; u < LL/256; u++) {
        int j = tid + u*256;
        float4 cj = g_atoms[1*NROW + b*LL + j];
        float dx = ci.x-cj.x, dy = ci.y-cj.y, dz = ci.z-cj.z;
        float d = sqrtf(dx*dx + dy*dy + dz*dz + 1e-6f);
        float v = mi * mask[b*LL + j] * d;
        s_d[j] = v;
        lmax = fmaxf(lmax, v);
    }
    #pragma unroll
    for (int o = 16; o > 0; o >>= 1) lmax = fmaxf(lmax, __shfl_xor_sync(0xffffffffu, lmax, o));
    if (lane == 0) s_fred[wid] = lmax;
    __syncthreads();
    if (wid == 0) {
        float v = (lane < 8) ? s_fred[lane] : 0.f;
        #pragma unroll
        for (int o = 4; o > 0; o >>= 1) v = fmaxf(v, __shfl_xor_sync(0xffffffffu, v, o));
        if (lane == 0) s_dmax = v;
    }
    __syncthreads();
    float Dmax = s_dmax;
    #pragma unroll
    for (int u = 0; u < LL/256; u++) {
        int j = tid + u*256;
        float m2 = mi * mask[b*LL + j];
        s_d[j] += (1.f - m2) * Dmax;
    }
    __syncthreads();

    const unsigned long long UMAX = 0xffffffffffffffffULL;
    for (int sel = 0; sel < KK; sel++) {
        unsigned long long best = UMAX;
        #pragma unroll
        for (int u = 0; u < LL/256; u++) {
            int j = tid + u*256;
            unsigned long long key = ((unsigned long long)__float_as_uint(s_d[j]) << 32) | (unsigned)j;
            best = min(best, key);
        }
        #pragma unroll
        for (int o = 16; o > 0; o >>= 1)
            best = min(best, __shfl_xor_sync(0xffffffffu, best, o));
        if (lane == 0) s_red[wid] = best;
        __syncthreads();
        if (tid == 0) {
            unsigned long long w = s_red[0];
            #pragma unroll
            for (int q = 1; q < 8; q++) w = min(w, s_red[q]);
            int jwin = (int)(w & 0xffffffffu);
            float val = __uint_as_float((unsigned)(w >> 32));
            g_Eidx[row*KK + sel] = jwin;
            g_Dnb[row*KK + sel] = val;
            if (out_idx) out_idx[row*KK + sel] = (float)jwin;
            s_d[jwin] = __int_as_float(0x7f800000);
        }
        __syncthreads();
    }
}

// ---------------- kernel 4: fused features + mma.sync GEMM + LayerNorm -------
// CTA: 128 edges x 128 features, K=256, 256 threads / 8 warps (warp = M16 x N128).
// A tile (features) packed bf16x2 hi/lo in smem, stride 36 words (conflict-free
// fragment loads). B fragments streamed from global in exact mma layout.
#define ASTRIDE 36

__global__ void __launch_bounds__(256)
k_fused(const void* __restrict__ residx, const void* __restrict__ chains,
        const float* __restrict__ ln_g, const float* __restrict__ ln_b,
        float* __restrict__ out) {
    __shared__ uint32_t sA_hi[128*ASTRIDE];
    __shared__ uint32_t sA_lo[128*ASTRIDE];
    __shared__ int s_dcode[128];

    int tid  = threadIdx.x;
    int wid  = tid >> 5;
    int lane = tid & 31;
    int g    = lane >> 2;
    int tig  = lane & 3;
    int eloc = tid & 127;
    int half = tid >> 7;

    // ---- per-edge geometry (both half-threads compute the same edge) ----
    int e   = blockIdx.x * 128 + eloc;
    int row = e / KK;
    int b   = row >> 11;
    int j   = g_Eidx[e];
    int rowj = (b << 11) + j;

    float4 Ai[4], Aj[4];
    #pragma unroll
    for (int a = 0; a < 4; a++) { Ai[a] = g_atoms[a*NROW + row]; Aj[a] = g_atoms[a*NROW + rowj]; }

    float dst[16];
    dst[0] = g_Dnb[e];
    #pragma unroll
    for (int p = 1; p < 16; p++) {
        float4 A = Ai[c_pa[p]], Bv = Aj[c_pb[p]];
        float dx = A.x-Bv.x, dy = A.y-Bv.y, dz = A.z-Bv.z;
        dst[p] = sqrtf(dx*dx + dy*dy + dz*dz + 1e-6f);
    }

    // positional code for this edge
    if (half == 0) {
        int is32 = g_idx32;
        int ri = read_idx(residx, row, is32);
        int rj = read_idx(residx, rowj, is32);
        int ci = read_idx(chains, row, is32);
        int cj = read_idx(chains, rowj, is32);
        int off = ri - rj + 32;
        off = max(0, min(64, off));
        s_dcode[eloc] = (ci == cj) ? off : 65;
    }

    float acc[16][4];
    #pragma unroll
    for (int t = 0; t < 16; t++)
        #pragma unroll
        for (int q = 0; q < 4; q++) acc[t][q] = 0.f;

    int rA0 = wid*16 + g;       // A-fragment rows for this lane
    int rA1 = rA0 + 8;

    // ---- K loop: 4 chunks of 64 ----
    for (int kc = 0; kc < NC; kc += 64) {
        __syncthreads();
        // features for this chunk: thread covers 16 k-pairs of its edge
        #pragma unroll
        for (int u = 0; u < 16; u++) {
            int kpl = half*16 + u;          // chunk-local k-pair
            int c0  = kc + kpl*2;
            int p   = c0 >> 4, m = c0 & 15;
            float mu0 = 2.0f + (float)m     * (20.0f/15.0f);
            float mu1 = 2.0f + (float)(m+1) * (20.0f/15.0f);
            float z0 = (dst[p] - mu0) * 0.8f;
            float z1 = (dst[p] - mu1) * 0.8f;
            float v0 = __expf(-z0*z0);
            float v1 = __expf(-z1*z1);
            __nv_bfloat16 h0 = __float2bfloat16(v0);
            __nv_bfloat16 h1 = __float2bfloat16(v1);
            sA_hi[eloc*ASTRIDE + kpl] =
                (uint32_t)__bfloat16_as_ushort(h0) | ((uint32_t)__bfloat16_as_ushort(h1) << 16);
            sA_lo[eloc*ASTRIDE + kpl] =
                pack_bf16x2(v0 - __bfloat162float(h0), v1 - __bfloat162float(h1));
        }
        __syncthreads();

        #pragma unroll
        for (int s = 0; s < 4; s++) {
            int kb = s*8 + tig;
            uint32_t ah0 = sA_hi[rA0*ASTRIDE + kb];
            uint32_t ah1 = sA_hi[rA1*ASTRIDE + kb];
            uint32_t ah2 = sA_hi[rA0*ASTRIDE + kb + 4];
            uint32_t ah3 = sA_hi[rA1*ASTRIDE + kb + 4];
            uint32_t al0 = sA_lo[rA0*ASTRIDE + kb];
            uint32_t al1 = sA_lo[rA1*ASTRIDE + kb];
            uint32_t al2 = sA_lo[rA0*ASTRIDE + kb + 4];
            uint32_t al3 = sA_lo[rA1*ASTRIDE + kb + 4];
            int sg = (kc >> 4) + s;
            const uint2* bh = (const uint2*)g_Bh + (size_t)(sg*16)*32 + lane;
            const uint2* bl = (const uint2*)g_Bl + (size_t)(sg*16)*32 + lane;
            #pragma unroll
            for (int t = 0; t < 16; t++) {
                uint2 vh = bh[t*32];
                uint2 vl = bl[t*32];
                MMA_BF16(acc[t], ah0, ah1, ah2, ah3, vh.x, vh.y);
                MMA_BF16(acc[t], al0, al1, al2, al3, vh.x, vh.y);
                MMA_BF16(acc[t], ah0, ah1, ah2, ah3, vl.x, vl.y);
            }
        }
    }

    // ---- epilogue: + positional, LayerNorm per edge row, store -------------
    // lane holds, for edges (wid*16+g) and (+8), cols n = t*8 + tig*2 + {0,1}
    #pragma unroll
    for (int er = 0; er < 2; er++) {
        int el = wid*16 + g + er*8;
        int eo = blockIdx.x * 128 + el;
        const float* pw = g_PW + s_dcode[el]*NF;
        float sum = 0.f, sum2 = 0.f;
        #pragma unroll
        for (int t = 0; t < 16; t++) {
            int n = t*8 + tig*2;
            float v0 = acc[t][er*2+0] + pw[n];
            float v1 = acc[t][er*2+1] + pw[n+1];
            acc[t][er*2+0] = v0;
            acc[t][er*2+1] = v1;
            sum  += v0 + v1;
            sum2 += v0*v0 + v1*v1;
        }
        // reduce across the 4 lanes of the quad (same g, tig = 0..3)
        sum  += __shfl_xor_sync(0xffffffffu, sum, 1);
        sum  += __shfl_xor_sync(0xffffffffu, sum, 2);
        sum2 += __shfl_xor_sync(0xffffffffu, sum2, 1);
        sum2 += __shfl_xor_sync(0xffffffffu, sum2, 2);
        float muv = sum * (1.f/128.f);
        float var = sum2 * (1.f/128.f) - muv*muv;
        float rstd = rsqrtf(var + 1e-5f);
        float* dsto = out + (size_t)eo * NF;
        #pragma unroll
        for (int t = 0; t < 16; t++) {
            int n = t*8 + tig*2;
            float2 o2;
            o2.x = (acc[t][er*2+0] - muv)*rstd*ln_g[n]   + ln_b[n];
            o2.y = (acc[t][er*2+1] - muv)*rstd*ln_g[n+1] + ln_b[n+1];
            *(float2*)(dsto + n) = o2;
        }
    }
}

// ---------------- launch ------------------------------------------------------
extern "C" void kernel_launch(void* const* d_in, const int* in_sizes, int n_in,
                              void* d_out, int out_size) {
    const float* X      = (const float*)d_in[0];
    const float* mask   = (const float*)d_in[1];
    const void*  residx = d_in[2];
    const void*  chains = d_in[3];
    const float* pe_w   = (const float*)d_in[4];
    const float* pe_b   = (const float*)d_in[5];
    const float* edge_w = (const float*)d_in[6];
    const float* ln_g   = (const float*)d_in[7];
    const float* ln_b   = (const float*)d_in[8];
    float* out = (float*)d_out;
    float* out_idx = ((size_t)out_size >= (size_t)NEDGE*NF + NEDGE)
                     ? out + (size_t)NEDGE*NF : nullptr;

    k_detect<<<1, 1>>>(residx);
    k_coords<<<(NROW + 255)/256, 256>>>(X);
    k_bfrag<<<(16*16*32*2 + 255)/256, 256>>>(edge_w);
    k_pw<<<66, 128>>>(edge_w, pe_w, pe_b);
    k_topk<<<NROW, 256>>>(mask, out_idx);
    k_fused<<<NTILE, 256>>>(residx, chains, ln_g, ln_b, out);
}

// round 8
// speedup vs baseline: 1.6716x; 1.2110x over previous
#include <cuda_runtime.h>
#include <cuda_bf16.h>
#include <math.h>
#include <stdint.h>

#define BB 4
#define LL 2048
#define KK 30
#define NROW (BB*LL)        // 8192
#define NEDGE (NROW*KK)     // 245760
#define NTILE (NEDGE/128)   // 1920
#define NF 128
#define NC 256              // RBF feature count (K of the GEMM)

// ---------------- device scratch ---------------------------------------------
__device__ float4   g_atoms[4*NROW];
__device__ int      g_Eidx[NEDGE];
__device__ float    g_Dnb[NEDGE];
__device__ __align__(16) uint32_t g_Bh[16*16*32*2];   // B frags (bf16 hi) [sg][t][lane][w]
__device__ __align__(16) uint32_t g_Bl[16*16*32*2];   // B frags (bf16 lo)
__device__ float    g_PW[66*NF];        // positional lookup [dcode][f]
__device__ int      g_idx32;

__constant__ int c_pa[16] = {1,0,2,3,1,1,1,0,0,3,0,2,3,2,3,2};
__constant__ int c_pb[16] = {1,0,2,3,0,2,3,2,3,2,1,1,1,0,0,3};

__device__ __forceinline__ int read_idx(const void* p, int i, int is32) {
    if (is32) return ((const int*)p)[i];
    return (int)((const long long*)p)[i];
}

__device__ __forceinline__ uint32_t pack_bf16x2(float lo_v, float hi_v) {
    __nv_bfloat16 a = __float2bfloat16(lo_v);
    __nv_bfloat16 b = __float2bfloat16(hi_v);
    return (uint32_t)__bfloat16_as_ushort(a) | ((uint32_t)__bfloat16_as_ushort(b) << 16);
}

#define MMA_BF16(d, a0, a1, a2, a3, b0, b1) \
    asm volatile("mma.sync.aligned.m16n8k16.row.col.f32.bf16.bf16.f32 " \
        "{%0,%1,%2,%3}, {%4,%5,%6,%7}, {%8,%9}, {%0,%1,%2,%3};" \
        : "+f"((d)[0]), "+f"((d)[1]), "+f"((d)[2]), "+f"((d)[3]) \
        : "r"(a0), "r"(a1), "r"(a2), "r"(a3), "r"(b0), "r"(b1))

// ---------------- kernel 0: detect int32 vs int64 ----------------------------
__global__ void k_detect(const void* residx) {
    const int* p = (const int*)residx;
    g_idx32 = (p[1] == 1 && p[2] == 2) ? 1 : 0;
}

// ---------------- kernel 1: atoms + virtual Cb -------------------------------
__global__ void k_coords(const float* __restrict__ X) {
    int t = blockIdx.x * blockDim.x + threadIdx.x;
    if (t >= NROW) return;
    const float* x = X + (size_t)t * 12;
    float Nx=x[0],Ny=x[1],Nz=x[2];
    float Cx=x[3],Cy=x[4],Cz=x[5];
    float Ax=x[6],Ay=x[7],Az=x[8];
    float bx=Ax-Nx, by=Ay-Ny, bz=Az-Nz;
    float cx=Cx-Ax, cy=Cy-Ay, cz=Cz-Az;
    float ax=by*cz-bz*cy, ay=bz*cx-bx*cz, az=bx*cy-by*cx;
    float Bx = -0.58273431f*ax + 0.56802827f*bx - 0.54067466f*cx + Ax;
    float By = -0.58273431f*ay + 0.56802827f*by - 0.54067466f*cy + Ay;
    float Bz = -0.58273431f*az + 0.56802827f*bz - 0.54067466f*cz + Az;
    g_atoms[0*NROW + t] = make_float4(Nx,Ny,Nz,0.f);
    g_atoms[1*NROW + t] = make_float4(Cx,Cy,Cz,0.f);
    g_atoms[2*NROW + t] = make_float4(Ax,Ay,Az,0.f);
    g_atoms[3*NROW + t] = make_float4(Bx,By,Bz,0.f);
}

// ---------------- kernel 2a: weights -> mma B-fragment layout (hi/lo) --------
__global__ void k_bfrag(const float* __restrict__ edge_w) {
    int widx = blockIdx.x * blockDim.x + threadIdx.x;
    if (widx >= 16*16*32*2) return;
    int sg   = widx >> 10;
    int t    = (widx >> 6) & 15;
    int lane = (widx >> 1) & 31;
    int wsel = widx & 1;
    int n  = t*8 + (lane >> 2);
    int k0 = sg*16 + (lane & 3)*2 + wsel*8;
    float w0 = edge_w[n*272 + 16 + k0];
    float w1 = edge_w[n*272 + 16 + k0 + 1];
    __nv_bfloat16 h0 = __float2bfloat16(w0);
    __nv_bfloat16 h1 = __float2bfloat16(w1);
    float l0 = w0 - __bfloat162float(h0);
    float l1 = w1 - __bfloat162float(h1);
    g_Bh[widx] = (uint32_t)__bfloat16_as_ushort(h0) | ((uint32_t)__bfloat16_as_ushort(h1) << 16);
    g_Bl[widx] = pack_bf16x2(l0, l1);
}

// ---------------- kernel 2b: positional lookup table -------------------------
__global__ void k_pw(const float* __restrict__ edge_w, const float* __restrict__ pe_w,
                     const float* __restrict__ pe_b) {
    int d = blockIdx.x;
    int f = threadIdx.x;
    float s = 0.f;
    #pragma unroll
    for (int n = 0; n < 16; n++)
        s += edge_w[f*272 + n] * (pe_w[n*66 + d] + pe_b[n]);
    g_PW[d*NF + f] = s;
}

// ---------------- kernel 3: top-k nearest C-C per row (REDUX-based) ----------
__global__ void k_topk(const float* __restrict__ mask, float* __restrict__ out_idx) {
    __shared__ float s_d[LL];
    __shared__ float s_fred[8];
    __shared__ unsigned s_redb[8];
    __shared__ unsigned s_redj[8];
    __shared__ float s_dmax;

    int row = blockIdx.x;
    int b = row / LL;
    int tid = threadIdx.x;
    int lane = tid & 31, wid = tid >> 5;

    float4 ci = g_atoms[1*NROW + row];
    float mi = mask[row];
    float lmax = 0.f;
    #pragma unroll
    for (int u = 0; u < LL/256; u++) {
        int j = tid + u*256;
        float4 cj = g_atoms[1*NROW + b*LL + j];
        float dx = ci.x-cj.x, dy = ci.y-cj.y, dz = ci.z-cj.z;
        float d = sqrtf(dx*dx + dy*dy + dz*dz + 1e-6f);
        float v = mi * mask[b*LL + j] * d;
        s_d[j] = v;
        lmax = fmaxf(lmax, v);
    }
    #pragma unroll
    for (int o = 16; o > 0; o >>= 1) lmax = fmaxf(lmax, __shfl_xor_sync(0xffffffffu, lmax, o));
    if (lane == 0) s_fred[wid] = lmax;
    __syncthreads();
    if (wid == 0) {
        float v = (lane < 8) ? s_fred[lane] : 0.f;
        #pragma unroll
        for (int o = 4; o > 0; o >>= 1) v = fmaxf(v, __shfl_xor_sync(0xffffffffu, v, o));
        if (lane == 0) s_dmax = v;
    }
    __syncthreads();
    float Dmax = s_dmax;
    #pragma unroll
    for (int u = 0; u < LL/256; u++) {
        int j = tid + u*256;
        float m2 = mi * mask[b*LL + j];
        s_d[j] += (1.f - m2) * Dmax;
    }
    __syncthreads();

    for (int sel = 0; sel < KK; sel++) {
        unsigned bb = 0xFFFFFFFFu; unsigned bj = 0;
        #pragma unroll
        for (int u = 0; u < LL/256; u++) {
            int j = tid + u*256;
            unsigned kb = __float_as_uint(s_d[j]);   // nonneg floats: bit-monotonic
            if (kb < bb) { bb = kb; bj = (unsigned)j; }
        }
        unsigned r1 = __reduce_min_sync(0xffffffffu, bb);
        unsigned r2 = __reduce_min_sync(0xffffffffu, (bb == r1) ? bj : 0xFFFFFFFFu);
        if (lane == 0) { s_redb[wid] = r1; s_redj[wid] = r2; }
        __syncthreads();
        if (wid == 0) {
            unsigned wb = (lane < 8) ? s_redb[lane] : 0xFFFFFFFFu;
            unsigned wj = (lane < 8) ? s_redj[lane] : 0xFFFFFFFFu;
            unsigned m1 = __reduce_min_sync(0xffffffffu, wb);
            unsigned mj = __reduce_min_sync(0xffffffffu, (wb == m1) ? wj : 0xFFFFFFFFu);
            if (lane == 0) {
                g_Eidx[row*KK + sel] = (int)mj;
                g_Dnb[row*KK + sel]  = __uint_as_float(m1);
                if (out_idx) out_idx[row*KK + sel] = (float)mj;
                s_d[mj] = __int_as_float(0x7f800000);  // +inf
            }
        }
        __syncthreads();
    }
}

// ---------------- kernel 4: fused features + mma.sync GEMM + LayerNorm -------
// CTA: 128 edges x 128 features, K=256, 256 threads / 8 warps.
// A (features) bf16x2 hi/lo in smem (stride 36, conflict-free fragment reads).
// B staged per 64-K chunk into smem (32KB), inner loop reads via LDS.64.
#define ASTRIDE 36
#define SW_AHI  0
#define SW_ALO  (128*ASTRIDE)              // 4608
#define SW_BHI  (2*128*ASTRIDE)            // 9216
#define SW_BLO  (2*128*ASTRIDE + 4096)     // 13312
#define SW_DC   (2*128*ASTRIDE + 8192)     // 17408
#define SMEM_WORDS (SW_DC + 128)
#define SMEM_BYTES (SMEM_WORDS*4)

__global__ void __launch_bounds__(256)
k_fused(const void* __restrict__ residx, const void* __restrict__ chains,
        const float* __restrict__ ln_g, const float* __restrict__ ln_b,
        float* __restrict__ out) {
    extern __shared__ uint32_t smw[];
    uint32_t* sA_hi = smw + SW_AHI;
    uint32_t* sA_lo = smw + SW_ALO;
    uint32_t* sB_hi = smw + SW_BHI;
    uint32_t* sB_lo = smw + SW_BLO;
    int*      s_dcode = (int*)(smw + SW_DC);

    int tid  = threadIdx.x;
    int wid  = tid >> 5;
    int lane = tid & 31;
    int g    = lane >> 2;
    int tig  = lane & 3;
    int eloc = tid & 127;
    int half = tid >> 7;

    // ---- per-edge geometry (both half-threads compute the same edge) ----
    int e   = blockIdx.x * 128 + eloc;
    int row = e / KK;
    int b   = row >> 11;
    int j   = g_Eidx[e];
    int rowj = (b << 11) + j;

    float4 Ai[4], Aj[4];
    #pragma unroll
    for (int a = 0; a < 4; a++) { Ai[a] = g_atoms[a*NROW + row]; Aj[a] = g_atoms[a*NROW + rowj]; }

    float dst[16];
    dst[0] = g_Dnb[e];
    #pragma unroll
    for (int p = 1; p < 16; p++) {
        float4 A = Ai[c_pa[p]], Bv = Aj[c_pb[p]];
        float dx = A.x-Bv.x, dy = A.y-Bv.y, dz = A.z-Bv.z;
        dst[p] = sqrtf(dx*dx + dy*dy + dz*dz + 1e-6f);
    }

    if (half == 0) {
        int is32 = g_idx32;
        int ri = read_idx(residx, row, is32);
        int rj = read_idx(residx, rowj, is32);
        int ci = read_idx(chains, row, is32);
        int cj = read_idx(chains, rowj, is32);
        int off = ri - rj + 32;
        off = max(0, min(64, off));
        s_dcode[eloc] = (ci == cj) ? off : 65;
    }

    float acc[16][4];
    #pragma unroll
    for (int t = 0; t < 16; t++)
        #pragma unroll
        for (int q = 0; q < 4; q++) acc[t][q] = 0.f;

    int rA0 = wid*16 + g;
    int rA1 = rA0 + 8;

    // ---- K loop: 4 chunks of 64 ----
    for (int kc = 0; kc < NC; kc += 64) {
        __syncthreads();
        // stage B chunk: 4 sgs = 4096 words each of hi/lo.
        // word base = sg_start * 1024 = (kc/16)*1024   <-- FIXED (was *1024*4, OOB)
        {
            const uint4* gh = (const uint4*)(g_Bh + (kc >> 4)*1024);
            const uint4* gl = (const uint4*)(g_Bl + (kc >> 4)*1024);
            uint4* shv = (uint4*)sB_hi;
            uint4* slv = (uint4*)sB_lo;
            #pragma unroll
            for (int r = 0; r < 4; r++) {
                shv[tid + r*256] = gh[tid + r*256];
                slv[tid + r*256] = gl[tid + r*256];
            }
        }
        // features for this chunk: thread covers 16 k-pairs of its edge
        #pragma unroll
        for (int u = 0; u < 16; u++) {
            int kpl = half*16 + u;
            int c0  = kc + kpl*2;
            int p   = c0 >> 4, m = c0 & 15;
            float mu0 = 2.0f + (float)m     * (20.0f/15.0f);
            float mu1 = 2.0f + (float)(m+1) * (20.0f/15.0f);
            float z0 = (dst[p] - mu0) * 0.8f;
            float z1 = (dst[p] - mu1) * 0.8f;
            float v0 = __expf(-z0*z0);
            float v1 = __expf(-z1*z1);
            __nv_bfloat16 h0 = __float2bfloat16(v0);
            __nv_bfloat16 h1 = __float2bfloat16(v1);
            sA_hi[eloc*ASTRIDE + kpl] =
                (uint32_t)__bfloat16_as_ushort(h0) | ((uint32_t)__bfloat16_as_ushort(h1) << 16);
            sA_lo[eloc*ASTRIDE + kpl] =
                pack_bf16x2(v0 - __bfloat162float(h0), v1 - __bfloat162float(h1));
        }
        __syncthreads();

        #pragma unroll
        for (int s = 0; s < 4; s++) {
            int kb = s*8 + tig;
            uint32_t ah0 = sA_hi[rA0*ASTRIDE + kb];
            uint32_t ah1 = sA_hi[rA1*ASTRIDE + kb];
            uint32_t ah2 = sA_hi[rA0*ASTRIDE + kb + 4];
            uint32_t ah3 = sA_hi[rA1*ASTRIDE + kb + 4];
            uint32_t al0 = sA_lo[rA0*ASTRIDE + kb];
            uint32_t al1 = sA_lo[rA1*ASTRIDE + kb];
            uint32_t al2 = sA_lo[rA0*ASTRIDE + kb + 4];
            uint32_t al3 = sA_lo[rA1*ASTRIDE + kb + 4];
            const uint2* bh = (const uint2*)sB_hi + (size_t)(s*16)*32 + lane;
            const uint2* bl = (const uint2*)sB_lo + (size_t)(s*16)*32 + lane;
            #pragma unroll
            for (int t = 0; t < 16; t++) {
                uint2 vh = bh[t*32];
                uint2 vl = bl[t*32];
                MMA_BF16(acc[t], ah0, ah1, ah2, ah3, vh.x, vh.y);
                MMA_BF16(acc[t], al0, al1, al2, al3, vh.x, vh.y);
                MMA_BF16(acc[t], ah0, ah1, ah2, ah3, vl.x, vl.y);
            }
        }
    }

    // ---- epilogue: + positional, LayerNorm per edge row, store -------------
    #pragma unroll
    for (int er = 0; er < 2; er++) {
        int el = wid*16 + g + er*8;
        int eo = blockIdx.x * 128 + el;
        const float* pw = g_PW + s_dcode[el]*NF;
        float sum = 0.f, sum2 = 0.f;
        #pragma unroll
        for (int t = 0; t < 16; t++) {
            int n = t*8 + tig*2;
            float v0 = acc[t][er*2+0] + pw[n];
            float v1 = acc[t][er*2+1] + pw[n+1];
            acc[t][er*2+0] = v0;
            acc[t][er*2+1] = v1;
            sum  += v0 + v1;
            sum2 += v0*v0 + v1*v1;
        }
        sum  += __shfl_xor_sync(0xffffffffu, sum, 1);
        sum  += __shfl_xor_sync(0xffffffffu, sum, 2);
        sum2 += __shfl_xor_sync(0xffffffffu, sum2, 1);
        sum2 += __shfl_xor_sync(0xffffffffu, sum2, 2);
        float muv = sum * (1.f/128.f);
        float var = sum2 * (1.f/128.f) - muv*muv;
        float rstd = rsqrtf(var + 1e-5f);
        float* dsto = out + (size_t)eo * NF;
        #pragma unroll
        for (int t = 0; t < 16; t++) {
            int n = t*8 + tig*2;
            float2 o2;
            o2.x = (acc[t][er*2+0] - muv)*rstd*ln_g[n]   + ln_b[n];
            o2.y = (acc[t][er*2+1] - muv)*rstd*ln_g[n+1] + ln_b[n+1];
            *(float2*)(dsto + n) = o2;
        }
    }
}

// ---------------- launch ------------------------------------------------------
extern "C" void kernel_launch(void* const* d_in, const int* in_sizes, int n_in,
                              void* d_out, int out_size) {
    const float* X      = (const float*)d_in[0];
    const float* mask   = (const float*)d_in[1];
    const void*  residx = d_in[2];
    const void*  chains = d_in[3];
    const float* pe_w   = (const float*)d_in[4];
    const float* pe_b   = (const float*)d_in[5];
    const float* edge_w = (const float*)d_in[6];
    const float* ln_g   = (const float*)d_in[7];
    const float* ln_b   = (const float*)d_in[8];
    float* out = (float*)d_out;
    float* out_idx = ((size_t)out_size >= (size_t)NEDGE*NF + NEDGE)
                     ? out + (size_t)NEDGE*NF : nullptr;

    cudaFuncSetAttribute(k_fused, cudaFuncAttributeMaxDynamicSharedMemorySize, SMEM_BYTES);

    // launch index 3 gets profiled -> place k_topk there
    k_detect<<<1, 1>>>(residx);                        // 0
    k_coords<<<(NROW + 255)/256, 256>>>(X);            // 1
    k_bfrag<<<(16*16*32*2 + 255)/256, 256>>>(edge_w);  // 2
    k_topk<<<NROW, 256>>>(mask, out_idx);              // 3 (profiled)
    k_pw<<<66, 128>>>(edge_w, pe_w, pe_b);             // 4
    k_fused<<<NTILE, 256, SMEM_BYTES>>>(residx, chains, ln_g, ln_b, out);  // 5
}